// round 6
// baseline (speedup 1.0000x reference)
#include <cuda_runtime.h>
#include <utility>

#define BATCH      16384
#define MAX_JETS   10
#define MAX_PAIRS  45
#define NF         64
#define NF4        16          // float4 per feature row
#define THREADS    256
#define NSTORE     23          // ceil(45/2) STG.128 per row

// L2 evict-last via cache-hint policy register (the inline .L2::evict_last
// qualifier is only legal on v8.b32/v4.b64 loads; the createpolicy +
// ld...L2::cache_hint form works for any width).
__device__ __forceinline__ unsigned long long mk_evict_last_policy() {
    unsigned long long pol;
    asm("createpolicy.fractional.L2::evict_last.b64 %0, 1.0;" : "=l"(pol));
    return pol;
}
__device__ __forceinline__ float4 ldg_el(const float4* p, unsigned long long pol) {
    float4 v;
    asm("ld.global.nc.L2::cache_hint.v4.f32 {%0,%1,%2,%3}, [%4], %5;"
        : "=f"(v.x), "=f"(v.y), "=f"(v.z), "=f"(v.w)
        : "l"(p), "l"(pol));
    return v;
}
__device__ __forceinline__ int ldg_el_i32(const int* p, unsigned long long pol) {
    int v;
    asm("ld.global.nc.L2::cache_hint.b32 %0, [%1], %2;"
        : "=r"(v) : "l"(p), "l"(pol));
    return v;
}

// Compile-time lexicographic pair tables (itertools.combinations order)
__host__ __device__ constexpr int pair_a(int n, int p) {
    int idx = 0;
    for (int a = 0; a < n; a++)
        for (int c = a + 1; c < n; c++) { if (idx == p) return a; idx++; }
    return 0;
}
__host__ __device__ constexpr int pair_c(int n, int p) {
    int idx = 0;
    for (int a = 0; a < n; a++)
        for (int c = a + 1; c < n; c++) { if (idx == p) return c; idx++; }
    return 0;
}

template<int N, int S>
__device__ __forceinline__
void do_store(const float4 (&j)[MAX_JETS], float4* __restrict__ dst,
              int lane, int half)
{
    constexpr int NP = N * (N - 1) / 2;
    constexpr int P0 = 2 * S;
    constexpr int P1 = 2 * S + 1;

    float4 v0 = make_float4(0.f, 0.f, 0.f, 0.f);
    float4 v1 = make_float4(0.f, 0.f, 0.f, 0.f);

    if constexpr (P0 < NP) {
        constexpr int A = pair_a(N, P0), C = pair_c(N, P0);
        v0.x = j[A].x + j[C].x;  v0.y = j[A].y + j[C].y;
        v0.z = j[A].z + j[C].z;  v0.w = j[A].w + j[C].w;
    }
    if constexpr (P1 < NP) {
        constexpr int A = pair_a(N, P1), C = pair_c(N, P1);
        v1.x = j[A].x + j[C].x;  v1.y = j[A].y + j[C].y;
        v1.z = j[A].z + j[C].z;  v1.w = j[A].w + j[C].w;
    }

    const float4 v = half ? v1 : v0;

    if constexpr (S < NSTORE - 1) {
        __stcs(&dst[S * 32 + lane], v);        // full-warp 512B store
    } else {
        if (half == 0)                         // pair 45 doesn't exist
            __stcs(&dst[S * 32 + lane], v);    // half-warp 256B store
    }
}

template<int N, int... S>
__device__ __forceinline__
void emit_stores(const float4 (&j)[MAX_JETS], float4* __restrict__ dst,
                 int lane, int half, std::integer_sequence<int, S...>)
{
    (do_store<N, S>(j, dst, lane, half), ...);
}

template<int N>
__device__ __forceinline__
void row_task(const float4* __restrict__ src, float4* __restrict__ dst,
              int lane, unsigned long long pol)
{
    const int half = lane >> 4;
    const int col  = lane & 15;     // float4 column (both halves read same cols)

    float4 j[MAX_JETS];
    #pragma unroll
    for (int a = 0; a < N; a++)
        j[a] = ldg_el(&src[a * NF4 + col], pol);

    emit_stores<N>(j, dst, lane, half, std::make_integer_sequence<int, NSTORE>{});
}

__global__ __launch_bounds__(THREADS)
void create_pairs_sum_kernel(const float4* __restrict__ in,      // [BATCH, 10, 16]
                             const int*    __restrict__ jet_num, // [BATCH]
                             float4*       __restrict__ out,     // [BATCH, 45, 16]
                             float*        __restrict__ out_num) // [BATCH]
{
    const int warp = (blockIdx.x * THREADS + threadIdx.x) >> 5;  // one warp = one row
    const int lane = threadIdx.x & 31;

    const unsigned long long pol = mk_evict_last_policy();

    const float4* src = in  + (size_t)warp * (MAX_JETS  * NF4);
    float4*       dst = out + (size_t)warp * (MAX_PAIRS * NF4);

    const int n = ldg_el_i32(&jet_num[warp], pol);   // warp-uniform

    switch (n) {
        case 2:  row_task<2> (src, dst, lane, pol); break;
        case 3:  row_task<3> (src, dst, lane, pol); break;
        case 4:  row_task<4> (src, dst, lane, pol); break;
        case 5:  row_task<5> (src, dst, lane, pol); break;
        case 6:  row_task<6> (src, dst, lane, pol); break;
        case 7:  row_task<7> (src, dst, lane, pol); break;
        case 8:  row_task<8> (src, dst, lane, pol); break;
        case 9:  row_task<9> (src, dst, lane, pol); break;
        default: row_task<10>(src, dst, lane, pol); break;
    }

    if (lane == 0)
        out_num[warp] = (float)((n * (n - 1)) >> 1);
}

extern "C" void kernel_launch(void* const* d_in, const int* in_sizes, int n_in,
                              void* d_out, int out_size)
{
    const float4* in      = (const float4*)d_in[0];  // inputs   [16384,10,64] f32
    // d_in[1] = dict_vals — unused (pairs generated analytically, same order)
    const int*    jet_num = (const int*)   d_in[2];  // jet_num  [16384] i32

    float*  out_base  = (float*)d_out;
    float4* out_pairs = (float4*)out_base;                          // [16384,45,64]
    float*  out_num   = out_base + (size_t)BATCH * MAX_PAIRS * NF;  // [16384]

    const int nblocks = BATCH * 32 / THREADS;        // 2048
    create_pairs_sum_kernel<<<nblocks, THREADS>>>(in, jet_num, out_pairs, out_num);
}